// round 9
// baseline (speedup 1.0000x reference)
#include <cuda_runtime.h>
#include <cuda_fp16.h>
#include <cstdint>

// Problem constants (B=2, S=4096, D=H=512), softmax scale = sqrt(512/8)=8.
#define Bsz 2
#define Sq  4096
#define Dd  512
#define Hh  512

// Scratch (device globals: allocation inside kernel_launch is forbidden).
__device__ __half g_xh [(size_t)Bsz * Sq * Dd], g_xl [(size_t)Bsz * Sq * Dd];
__device__ __half g_Wqh[Dd * Hh], g_Wql[Dd * Hh];
__device__ __half g_Wkh[Dd * Hh], g_Wkl[Dd * Hh];
__device__ __half g_Wvh[Dd * Hh], g_Wvl[Dd * Hh];
__device__ __half g_Wmh[Hh * Hh], g_Wml[Hh * Hh];
__device__ __half g_qh [(size_t)Bsz * Sq * Hh], g_ql [(size_t)Bsz * Sq * Hh];
__device__ __half g_kh [(size_t)Bsz * Sq * Hh], g_kl [(size_t)Bsz * Sq * Hh];
__device__ float  g_v  [(size_t)Bsz * Sq * Hh];
__device__ __half g_vth[(size_t)Bsz * Sq * Hh], g_vtl[(size_t)Bsz * Sq * Hh];
__device__ float  g_sc [(size_t)Bsz * Sq * Sq];                    // 128 MB
__device__ __half g_ph [(size_t)Bsz * Sq * Sq];                    // 64 MB (unnormalized probs)
__device__ float  g_linv[(size_t)Bsz * Sq];                        // 1/rowsum
__device__ __half g_ath[(size_t)Bsz * Sq * Hh], g_atl[(size_t)Bsz * Sq * Hh];

// ---------------------------------------------------------------------------
// helpers
// ---------------------------------------------------------------------------
__device__ __forceinline__ uint32_t smem_u32(const void* p) {
    uint32_t a;
    asm("{ .reg .u64 t; cvta.to.shared.u64 t, %1; cvt.u32.u64 %0, t; }"
        : "=r"(a) : "l"(p));
    return a;
}
__device__ __forceinline__ void cp16(uint32_t smem, const void* g) {
    asm volatile("cp.async.cg.shared.global [%0], [%1], 16;"
                 :: "r"(smem), "l"(g) : "memory");
}
#define CP_COMMIT() asm volatile("cp.async.commit_group;" ::: "memory")
#define CP_WAIT(n)  asm volatile("cp.async.wait_group %0;" :: "n"(n) : "memory")

// m16n8k16 fp16 mma, fp32 accum. row.col => both operands K-major (NT GEMM).
__device__ __forceinline__ void mma16(float* c, const uint32_t* a, const uint32_t* b) {
    asm volatile(
        "mma.sync.aligned.m16n8k16.row.col.f32.f16.f16.f32 "
        "{%0,%1,%2,%3}, {%4,%5,%6,%7}, {%8,%9}, {%0,%1,%2,%3};"
        : "+f"(c[0]), "+f"(c[1]), "+f"(c[2]), "+f"(c[3])
        : "r"(a[0]), "r"(a[1]), "r"(a[2]), "r"(a[3]), "r"(b[0]), "r"(b[1]));
}

// ---------------------------------------------------------------------------
// fp16x3 GEMM:  C = rowscale[r] * (scale * (A @ W^T) + bscale * bias)
// A as (Ah, Al) fp16 pair (Al may be null -> 2-term mode), W as (Wh, Wl).
// Output fp32 Cf and/or fp16 pair (Ch, Cl). CTA tile 128x128, K-chunk 64.
// 512 threads = 16 warps (4 M x 4 N), warp tile 32x32. smem stride 36 b32.
// ---------------------------------------------------------------------------
#define BM 128
#define BN 128
#define KC 64
#define RS 36
#define PART (128 * RS)
#define STAGE (4 * PART)
#define SMEM_SZ (2 * STAGE * 4)        // 144 KB

__global__ __launch_bounds__(512, 1)
void k_hgemm(const __half* __restrict__ Ah, const __half* __restrict__ Al,
             const __half* __restrict__ Wh, const __half* __restrict__ Wl,
             const float* __restrict__ bias, const float* __restrict__ rowscale,
             float* __restrict__ Cf, __half* __restrict__ Ch, __half* __restrict__ Cl,
             int M, int N, int K, float scale, float bscale,
             long long sA, long long sW, long long sC,
             int skip_lower, int diag_kstart, int inv_mb)
{
    int nb = blockIdx.x, bz = blockIdx.z;
    int mb = inv_mb ? (gridDim.y - 1 - blockIdx.y) : blockIdx.y;
    if (skip_lower && nb < mb) return;          // block entirely masked (j < i)
    int hasAl = (Al != 0);
    Ah += (size_t)bz * sA;  if (hasAl) Al += (size_t)bz * sA;
    Wh += (size_t)bz * sW;  Wl += (size_t)bz * sW;
    if (Cf) Cf += (size_t)bz * sC;
    if (Ch) { Ch += (size_t)bz * sC; Cl += (size_t)bz * sC; }
    if (rowscale) rowscale += (size_t)bz * M;

    extern __shared__ uint32_t sm32[];
    uint32_t smb = smem_u32(sm32);

    int tid  = threadIdx.x;
    int warp = tid >> 5, lane = tid & 31;
    int wm = warp >> 2, wn = warp & 3;
    int g  = lane >> 2, q4 = lane & 3;
    int m0 = mb * BM, n0 = nb * BN;

    int kt0 = diag_kstart ? m0 : 0;
    int nch = (K - kt0) / KC;

    float acc[2][4][4];
    #pragma unroll
    for (int i = 0; i < 2; i++)
        #pragma unroll
        for (int j = 0; j < 4; j++)
            #pragma unroll
            for (int r = 0; r < 4; r++) acc[i][j][r] = 0.f;

    int lr  = tid >> 3;
    int seg = tid & 7;

    auto load_stage = [&](uint32_t sb, int kt) {
        #pragma unroll
        for (int j = 0; j < 2; j++) {
            int row = j * 64 + lr;
            uint32_t so = (uint32_t)(row * RS) * 4 + seg * 16;
            size_t ga = (size_t)(m0 + row) * K + kt + seg * 8;
            size_t gw = (size_t)(n0 + row) * K + kt + seg * 8;
            cp16(sb + so,                 Ah + ga);
            if (hasAl) cp16(sb + PART * 4 + so, Al + ga);
            cp16(sb + 2 * PART * 4 + so,  Wh + gw);
            cp16(sb + 3 * PART * 4 + so,  Wl + gw);
        }
    };

    load_stage(smb, kt0);
    CP_COMMIT();

    for (int ic = 0; ic < nch; ic++) {
        if (ic + 1 < nch) {
            load_stage(smb + ((ic + 1) & 1) * STAGE * 4, kt0 + (ic + 1) * KC);
            CP_COMMIT();
            CP_WAIT(1);
        } else {
            CP_WAIT(0);
        }
        __syncthreads();

        const uint32_t* S0 = sm32 + (ic & 1) * STAGE;
        const uint32_t* Ahs = S0;
        const uint32_t* Als = S0 + PART;
        const uint32_t* Bhs = S0 + 2 * PART;
        const uint32_t* Bls = S0 + 3 * PART;

        #pragma unroll
        for (int ks = 0; ks < 4; ks++) {
            int c0 = ks * 8 + q4;
            uint32_t ah[2][4], al[2][4];
            #pragma unroll
            for (int tm = 0; tm < 2; tm++) {
                int r = wm * 32 + tm * 16 + g;
                ah[tm][0] = Ahs[r * RS + c0];
                ah[tm][1] = Ahs[(r + 8) * RS + c0];
                ah[tm][2] = Ahs[r * RS + c0 + 4];
                ah[tm][3] = Ahs[(r + 8) * RS + c0 + 4];
                if (hasAl) {
                    al[tm][0] = Als[r * RS + c0];
                    al[tm][1] = Als[(r + 8) * RS + c0];
                    al[tm][2] = Als[r * RS + c0 + 4];
                    al[tm][3] = Als[(r + 8) * RS + c0 + 4];
                }
            }
            #pragma unroll
            for (int tn = 0; tn < 4; tn++) {
                int n = wn * 32 + tn * 8 + g;
                uint32_t bh[2], bl[2];
                bh[0] = Bhs[n * RS + c0];
                bh[1] = Bhs[n * RS + c0 + 4];
                bl[0] = Bls[n * RS + c0];
                bl[1] = Bls[n * RS + c0 + 4];
                #pragma unroll
                for (int tm = 0; tm < 2; tm++) {
                    mma16(acc[tm][tn], ah[tm], bh);          // hi*hi
                    mma16(acc[tm][tn], ah[tm], bl);          // hi*lo
                    if (hasAl) mma16(acc[tm][tn], al[tm], bh); // lo*hi
                }
            }
        }
        __syncthreads();
    }

    // ---- epilogue ----
    #pragma unroll
    for (int tm = 0; tm < 2; tm++) {
        int r = m0 + wm * 32 + tm * 16 + g;
        float rs0 = 1.f, rs1 = 1.f;
        if (rowscale) { rs0 = rowscale[r]; rs1 = rowscale[r + 8]; }
        #pragma unroll
        for (int tn = 0; tn < 4; tn++) {
            int cc = n0 + wn * 32 + tn * 8 + q4 * 2;
            float bv0 = 0.f, bv1 = 0.f;
            if (bias) {
                bv0 = bscale * __ldg(bias + cc);
                bv1 = bscale * __ldg(bias + cc + 1);
            }
            float v00 = (scale * acc[tm][tn][0] + bv0) * rs0;
            float v01 = (scale * acc[tm][tn][1] + bv1) * rs0;
            float v10 = (scale * acc[tm][tn][2] + bv0) * rs1;
            float v11 = (scale * acc[tm][tn][3] + bv1) * rs1;
            if (Cf) {
                *(float2*)(Cf + (size_t)r * N + cc)       = make_float2(v00, v01);
                *(float2*)(Cf + (size_t)(r + 8) * N + cc) = make_float2(v10, v11);
            }
            if (Ch) {
                __half h00 = __float2half_rn(v00), h01 = __float2half_rn(v01);
                __half h10 = __float2half_rn(v10), h11 = __float2half_rn(v11);
                *(__half2*)(Ch + (size_t)r * N + cc)       = __halves2half2(h00, h01);
                *(__half2*)(Ch + (size_t)(r + 8) * N + cc) = __halves2half2(h10, h11);
                *(__half2*)(Cl + (size_t)r * N + cc) = __halves2half2(
                    __float2half_rn(v00 - __half2float(h00)),
                    __float2half_rn(v01 - __half2float(h01)));
                *(__half2*)(Cl + (size_t)(r + 8) * N + cc) = __halves2half2(
                    __float2half_rn(v10 - __half2float(h10)),
                    __float2half_rn(v11 - __half2float(h11)));
            }
        }
    }
}

// ---------------------------------------------------------------------------
// Split fp32 -> fp16 hi/lo pair.
// ---------------------------------------------------------------------------
__global__ __launch_bounds__(256)
void k_split(const float* __restrict__ x, __half* __restrict__ h,
             __half* __restrict__ l, int n)
{
    for (int i = blockIdx.x * 256 + threadIdx.x; i < n; i += gridDim.x * 256) {
        float v = x[i];
        __half hh = __float2half_rn(v);
        h[i] = hh;
        l[i] = __float2half_rn(v - __half2float(hh));
    }
}

// ---------------------------------------------------------------------------
// 2-pass row softmax: single exp per element. Writes UNNORMALIZED p=exp(s-m)
// as fp16 for j in [i, S), zeros for [i_tile, i), and inv_l = 1/sum per row.
// Normalization is applied in the PV epilogue via rowscale.
// ---------------------------------------------------------------------------
__global__ __launch_bounds__(256)
void k_softmax(const float* __restrict__ Sc, __half* __restrict__ Ph,
               float* __restrict__ Linv)
{
    int i = blockIdx.x;
    int b = blockIdx.y;
    size_t off = ((size_t)b * Sq + i) * Sq;
    const float* row = Sc + off;
    __half* ph = Ph + off;
    int t = threadIdx.x;
    __shared__ float red[256];

    // pass 1: max over [i, S)
    float m = -3.402823466e38f;
    for (int j = i + t; j < Sq; j += 256) m = fmaxf(m, row[j]);
    red[t] = m; __syncthreads();
    for (int s = 128; s > 0; s >>= 1) {
        if (t < s) red[t] = fmaxf(red[t], red[t + s]);
        __syncthreads();
    }
    m = red[0];
    __syncthreads();

    // pass 2: exp once, write unnormalized p, accumulate sum
    float l = 0.f;
    for (int j = i + t; j < Sq; j += 256) {
        float e = __expf(row[j] - m);
        l += e;
        ph[j] = __float2half_rn(e);
    }
    // zero the masked prefix within this row's PV k-tile
    int i0 = i & ~(BM - 1);
    for (int j = i0 + t; j < i; j += 256) ph[j] = __float2half_rn(0.f);

    red[t] = l; __syncthreads();
    for (int s = 128; s > 0; s >>= 1) {
        if (t < s) red[t] += red[t + s];
        __syncthreads();
    }
    if (t == 0) Linv[(size_t)b * Sq + i] = 1.0f / red[0];
}

// ---------------------------------------------------------------------------
// Transpose v [S,H] -> vt [H,S] per batch, splitting to fp16 hi/lo.
// ---------------------------------------------------------------------------
__global__ __launch_bounds__(256)
void k_transpose_split(const float* __restrict__ V, __half* __restrict__ Th,
                       __half* __restrict__ Tl)
{
    __shared__ float t[32][33];
    int bz = blockIdx.z;
    const float* Vb = V + (size_t)bz * Sq * Hh;
    __half* Hb = Th + (size_t)bz * Sq * Hh;
    __half* Lb = Tl + (size_t)bz * Sq * Hh;
    int c0 = blockIdx.x * 32, r0 = blockIdx.y * 32;
    int tx = threadIdx.x & 31, ty = threadIdx.x >> 5;
    #pragma unroll
    for (int i = ty; i < 32; i += 8)
        t[i][tx] = Vb[(size_t)(r0 + i) * Hh + c0 + tx];
    __syncthreads();
    #pragma unroll
    for (int i = ty; i < 32; i += 8) {
        float v = t[tx][i];
        __half h = __float2half_rn(v);
        size_t o = (size_t)(c0 + i) * Sq + r0 + tx;
        Hb[o] = h;
        Lb[o] = __float2half_rn(v - __half2float(h));
    }
}

// ---------------------------------------------------------------------------
extern "C" void kernel_launch(void* const* d_in, const int* in_sizes, int n_in,
                              void* d_out, int out_size)
{
    (void)in_sizes; (void)n_in; (void)out_size;
    const float* x  = (const float*)d_in[0];
    const float* Wq = (const float*)d_in[1];
    const float* bq = (const float*)d_in[2];
    const float* Wk = (const float*)d_in[3];
    const float* bk = (const float*)d_in[4];
    const float* Wv = (const float*)d_in[5];
    const float* bv = (const float*)d_in[6];
    const float* Wm = (const float*)d_in[7];
    const float* bm = (const float*)d_in[8];
    float* out = (float*)d_out;

    __half *xh, *xl, *Wqh, *Wql, *Wkh, *Wkl, *Wvh, *Wvl, *Wmh, *Wml;
    __half *qh, *ql, *kh, *kl, *vth, *vtl, *ph, *ath, *atl;
    float *v, *sc, *linv;
    cudaGetSymbolAddress((void**)&xh,  g_xh);  cudaGetSymbolAddress((void**)&xl,  g_xl);
    cudaGetSymbolAddress((void**)&Wqh, g_Wqh); cudaGetSymbolAddress((void**)&Wql, g_Wql);
    cudaGetSymbolAddress((void**)&Wkh, g_Wkh); cudaGetSymbolAddress((void**)&Wkl, g_Wkl);
    cudaGetSymbolAddress((void**)&Wvh, g_Wvh); cudaGetSymbolAddress((void**)&Wvl, g_Wvl);
    cudaGetSymbolAddress((void**)&Wmh, g_Wmh); cudaGetSymbolAddress((void**)&Wml, g_Wml);
    cudaGetSymbolAddress((void**)&qh,  g_qh);  cudaGetSymbolAddress((void**)&ql,  g_ql);
    cudaGetSymbolAddress((void**)&kh,  g_kh);  cudaGetSymbolAddress((void**)&kl,  g_kl);
    cudaGetSymbolAddress((void**)&v,   g_v);
    cudaGetSymbolAddress((void**)&vth, g_vth); cudaGetSymbolAddress((void**)&vtl, g_vtl);
    cudaGetSymbolAddress((void**)&sc,  g_sc);
    cudaGetSymbolAddress((void**)&ph,  g_ph);
    cudaGetSymbolAddress((void**)&linv,g_linv);
    cudaGetSymbolAddress((void**)&ath, g_ath); cudaGetSymbolAddress((void**)&atl, g_atl);

    cudaFuncSetAttribute(k_hgemm, cudaFuncAttributeMaxDynamicSharedMemorySize, SMEM_SZ);

    dim3 blk(512);

    // Split inputs once.
    k_split<<<2048, 256>>>(x,  xh,  xl,  Bsz * Sq * Dd);
    k_split<<<256,  256>>>(Wq, Wqh, Wql, Dd * Hh);
    k_split<<<256,  256>>>(Wk, Wkh, Wkl, Dd * Hh);
    k_split<<<256,  256>>>(Wv, Wvh, Wvl, Dd * Hh);
    k_split<<<256,  256>>>(Wm, Wmh, Wml, Hh * Hh);

    dim3 gproj(Hh / BN, (Bsz * Sq) / BM, 1);      // 4 x 64

    // Projections (softmax 1/8 folded into q, incl. its bias).
    k_hgemm<<<gproj, blk, SMEM_SZ>>>(xh, xl, Wqh, Wql, bq, (float*)0, (float*)0, qh, ql,
                                     Bsz * Sq, Hh, Dd, 0.125f, 0.125f, 0, 0, 0, 0, 0, 0);
    k_hgemm<<<gproj, blk, SMEM_SZ>>>(xh, xl, Wkh, Wkl, bk, (float*)0, (float*)0, kh, kl,
                                     Bsz * Sq, Hh, Dd, 1.0f, 1.0f, 0, 0, 0, 0, 0, 0);
    k_hgemm<<<gproj, blk, SMEM_SZ>>>(xh, xl, Wvh, Wvl, bv, (float*)0, v, (__half*)0, (__half*)0,
                                     Bsz * Sq, Hh, Dd, 1.0f, 1.0f, 0, 0, 0, 0, 0, 0);

    // Scores (fp32), upper-triangular blocks only (nb >= mb).
    k_hgemm<<<dim3(Sq / BN, Sq / BM, Bsz), blk, SMEM_SZ>>>(
        qh, ql, kh, kl, (const float*)0, (float*)0, sc, (__half*)0, (__half*)0,
        Sq, Sq, Hh, 1.0f, 0.0f,
        (long long)Sq * Hh, (long long)Sq * Hh, (long long)Sq * Sq, 1, 0, 0);

    // 2-pass softmax -> unnormalized fp16 probs + inv rowsum.
    k_softmax<<<dim3(Sq, Bsz), 256>>>(sc, ph, linv);

    // vt = v^T (split), then attn = (P @ v) * inv_l, 2-term, heavy tiles first.
    k_transpose_split<<<dim3(Hh / 32, Sq / 32, Bsz), 256>>>(v, vth, vtl);
    k_hgemm<<<dim3(Hh / BN, Sq / BM, Bsz), blk, SMEM_SZ>>>(
        ph, (__half*)0, vth, vtl, (const float*)0, linv, (float*)0, ath, atl,
        Sq, Hh, Sq, 1.0f, 0.0f,
        (long long)Sq * Sq, (long long)Sq * Hh, (long long)Sq * Hh, 0, 1, 1);

    // out = 8 * attn @ Wm^T + bm  (NUM_HEADS folded into scale).
    k_hgemm<<<gproj, blk, SMEM_SZ>>>(ath, atl, Wmh, Wml, bm, (float*)0, out, (__half*)0, (__half*)0,
                                     Bsz * Sq, Hh, Dd, 8.0f, 1.0f, 0, 0, 0, 0, 0, 0);
}

// round 10
// speedup vs baseline: 1.1264x; 1.1264x over previous
#include <cuda_runtime.h>
#include <cuda_fp16.h>
#include <cstdint>

// Problem constants (B=2, S=4096, D=H=512), softmax scale = sqrt(512/8)=8.
#define Bsz 2
#define Sq  4096
#define Dd  512
#define Hh  512

// Scratch (device globals: allocation inside kernel_launch is forbidden).
__device__ __half g_xh [(size_t)Bsz * Sq * Dd], g_xl [(size_t)Bsz * Sq * Dd];
__device__ __half g_Wqh[Dd * Hh], g_Wql[Dd * Hh];
__device__ __half g_Wkh[Dd * Hh], g_Wkl[Dd * Hh];
__device__ __half g_Wvh[Dd * Hh], g_Wvl[Dd * Hh];
__device__ __half g_Wmh[Hh * Hh], g_Wml[Hh * Hh];
__device__ __half g_qh [(size_t)Bsz * Sq * Hh], g_ql [(size_t)Bsz * Sq * Hh];
__device__ __half g_kh [(size_t)Bsz * Sq * Hh], g_kl [(size_t)Bsz * Sq * Hh];
__device__ float  g_v  [(size_t)Bsz * Sq * Hh];
__device__ __half g_vth[(size_t)Bsz * Sq * Hh], g_vtl[(size_t)Bsz * Sq * Hh];
__device__ float  g_sc [(size_t)Bsz * Sq * Sq];                    // 128 MB
__device__ __half g_ph [(size_t)Bsz * Sq * Sq];                    // 64 MB (unnormalized probs)
__device__ float  g_linv[(size_t)Bsz * Sq];                        // 1/rowsum
__device__ __half g_ath[(size_t)Bsz * Sq * Hh], g_atl[(size_t)Bsz * Sq * Hh];

// ---------------------------------------------------------------------------
// helpers
// ---------------------------------------------------------------------------
__device__ __forceinline__ uint32_t smem_u32(const void* p) {
    uint32_t a;
    asm("{ .reg .u64 t; cvta.to.shared.u64 t, %1; cvt.u32.u64 %0, t; }"
        : "=r"(a) : "l"(p));
    return a;
}
__device__ __forceinline__ void cp16(uint32_t smem, const void* g) {
    asm volatile("cp.async.cg.shared.global [%0], [%1], 16;"
                 :: "r"(smem), "l"(g) : "memory");
}
#define CP_COMMIT() asm volatile("cp.async.commit_group;" ::: "memory")
#define CP_WAIT(n)  asm volatile("cp.async.wait_group %0;" :: "n"(n) : "memory")

// m16n8k16 fp16 mma, fp32 accum. row.col => both operands K-major (NT GEMM).
__device__ __forceinline__ void mma16(float* c, const uint32_t* a, const uint32_t* b) {
    asm volatile(
        "mma.sync.aligned.m16n8k16.row.col.f32.f16.f16.f32 "
        "{%0,%1,%2,%3}, {%4,%5,%6,%7}, {%8,%9}, {%0,%1,%2,%3};"
        : "+f"(c[0]), "+f"(c[1]), "+f"(c[2]), "+f"(c[3])
        : "r"(a[0]), "r"(a[1]), "r"(a[2]), "r"(a[3]), "r"(b[0]), "r"(b[1]));
}

// ---------------------------------------------------------------------------
// fp16x3 GEMM:  C = rowscale[r] * (scale * (A @ W^T) + bscale * bias)
// A as (Ah, Al) fp16 pair (Al may be null -> 2-term mode), W as (Wh, Wl).
// Output fp32 Cf and/or fp16 pair (Ch, Cl). CTA tile 128x128, K-chunk 64.
// 512 threads = 16 warps (4 M x 4 N), warp tile 32x32. smem stride 36 b32.
// ---------------------------------------------------------------------------
#define BM 128
#define BN 128
#define KC 64
#define RS 36
#define PART (128 * RS)
#define STAGE (4 * PART)
#define SMEM_SZ (2 * STAGE * 4)        // 144 KB

__global__ __launch_bounds__(512, 1)
void k_hgemm(const __half* __restrict__ Ah, const __half* __restrict__ Al,
             const __half* __restrict__ Wh, const __half* __restrict__ Wl,
             const float* __restrict__ bias, const float* __restrict__ rowscale,
             float* __restrict__ Cf, __half* __restrict__ Ch, __half* __restrict__ Cl,
             int M, int N, int K, float scale, float bscale,
             long long sA, long long sW, long long sC,
             int skip_lower, int diag_kstart)
{
    int nb = blockIdx.x, bz = blockIdx.z;
    int mb = blockIdx.y;
    if (skip_lower && nb < mb) return;          // block entirely masked (j < i)
    int hasAl = (Al != 0);
    Ah += (size_t)bz * sA;  if (hasAl) Al += (size_t)bz * sA;
    Wh += (size_t)bz * sW;  Wl += (size_t)bz * sW;
    if (Cf) Cf += (size_t)bz * sC;
    if (Ch) { Ch += (size_t)bz * sC; Cl += (size_t)bz * sC; }
    if (rowscale) rowscale += (size_t)bz * M;

    extern __shared__ uint32_t sm32[];
    uint32_t smb = smem_u32(sm32);

    int tid  = threadIdx.x;
    int warp = tid >> 5, lane = tid & 31;
    int wm = warp >> 2, wn = warp & 3;
    int g  = lane >> 2, q4 = lane & 3;
    int m0 = mb * BM, n0 = nb * BN;

    int kt0 = diag_kstart ? m0 : 0;
    int nch = (K - kt0) / KC;

    float acc[2][4][4];
    #pragma unroll
    for (int i = 0; i < 2; i++)
        #pragma unroll
        for (int j = 0; j < 4; j++)
            #pragma unroll
            for (int r = 0; r < 4; r++) acc[i][j][r] = 0.f;

    int lr  = tid >> 3;
    int seg = tid & 7;

    auto load_stage = [&](uint32_t sb, int kt) {
        #pragma unroll
        for (int j = 0; j < 2; j++) {
            int row = j * 64 + lr;
            uint32_t so = (uint32_t)(row * RS) * 4 + seg * 16;
            size_t ga = (size_t)(m0 + row) * K + kt + seg * 8;
            size_t gw = (size_t)(n0 + row) * K + kt + seg * 8;
            cp16(sb + so,                 Ah + ga);
            if (hasAl) cp16(sb + PART * 4 + so, Al + ga);
            cp16(sb + 2 * PART * 4 + so,  Wh + gw);
            cp16(sb + 3 * PART * 4 + so,  Wl + gw);
        }
    };

    load_stage(smb, kt0);
    CP_COMMIT();

    for (int ic = 0; ic < nch; ic++) {
        if (ic + 1 < nch) {
            load_stage(smb + ((ic + 1) & 1) * STAGE * 4, kt0 + (ic + 1) * KC);
            CP_COMMIT();
            CP_WAIT(1);
        } else {
            CP_WAIT(0);
        }
        __syncthreads();

        const uint32_t* S0 = sm32 + (ic & 1) * STAGE;
        const uint32_t* Ahs = S0;
        const uint32_t* Als = S0 + PART;
        const uint32_t* Bhs = S0 + 2 * PART;
        const uint32_t* Bls = S0 + 3 * PART;

        #pragma unroll
        for (int ks = 0; ks < 4; ks++) {
            int c0 = ks * 8 + q4;
            uint32_t ah[2][4], al[2][4];
            #pragma unroll
            for (int tm = 0; tm < 2; tm++) {
                int r = wm * 32 + tm * 16 + g;
                ah[tm][0] = Ahs[r * RS + c0];
                ah[tm][1] = Ahs[(r + 8) * RS + c0];
                ah[tm][2] = Ahs[r * RS + c0 + 4];
                ah[tm][3] = Ahs[(r + 8) * RS + c0 + 4];
                if (hasAl) {
                    al[tm][0] = Als[r * RS + c0];
                    al[tm][1] = Als[(r + 8) * RS + c0];
                    al[tm][2] = Als[r * RS + c0 + 4];
                    al[tm][3] = Als[(r + 8) * RS + c0 + 4];
                }
            }
            #pragma unroll
            for (int tn = 0; tn < 4; tn++) {
                int n = wn * 32 + tn * 8 + g;
                uint32_t bh[2], bl[2];
                bh[0] = Bhs[n * RS + c0];
                bh[1] = Bhs[n * RS + c0 + 4];
                bl[0] = Bls[n * RS + c0];
                bl[1] = Bls[n * RS + c0 + 4];
                #pragma unroll
                for (int tm = 0; tm < 2; tm++) {
                    mma16(acc[tm][tn], ah[tm], bh);            // hi*hi
                    mma16(acc[tm][tn], ah[tm], bl);            // hi*lo
                    if (hasAl) mma16(acc[tm][tn], al[tm], bh); // lo*hi
                }
            }
        }
        __syncthreads();
    }

    // ---- epilogue ----
    #pragma unroll
    for (int tm = 0; tm < 2; tm++) {
        int r = m0 + wm * 32 + tm * 16 + g;
        float rs0 = 1.f, rs1 = 1.f;
        if (rowscale) { rs0 = rowscale[r]; rs1 = rowscale[r + 8]; }
        #pragma unroll
        for (int tn = 0; tn < 4; tn++) {
            int cc = n0 + wn * 32 + tn * 8 + q4 * 2;
            float bv0 = 0.f, bv1 = 0.f;
            if (bias) {
                bv0 = bscale * __ldg(bias + cc);
                bv1 = bscale * __ldg(bias + cc + 1);
            }
            float v00 = (scale * acc[tm][tn][0] + bv0) * rs0;
            float v01 = (scale * acc[tm][tn][1] + bv1) * rs0;
            float v10 = (scale * acc[tm][tn][2] + bv0) * rs1;
            float v11 = (scale * acc[tm][tn][3] + bv1) * rs1;
            if (Cf) {
                *(float2*)(Cf + (size_t)r * N + cc)       = make_float2(v00, v01);
                *(float2*)(Cf + (size_t)(r + 8) * N + cc) = make_float2(v10, v11);
            }
            if (Ch) {
                __half h00 = __float2half_rn(v00), h01 = __float2half_rn(v01);
                __half h10 = __float2half_rn(v10), h11 = __float2half_rn(v11);
                *(__half2*)(Ch + (size_t)r * N + cc)       = __halves2half2(h00, h01);
                *(__half2*)(Ch + (size_t)(r + 8) * N + cc) = __halves2half2(h10, h11);
                *(__half2*)(Cl + (size_t)r * N + cc) = __halves2half2(
                    __float2half_rn(v00 - __half2float(h00)),
                    __float2half_rn(v01 - __half2float(h01)));
                *(__half2*)(Cl + (size_t)(r + 8) * N + cc) = __halves2half2(
                    __float2half_rn(v10 - __half2float(h10)),
                    __float2half_rn(v11 - __half2float(h11)));
            }
        }
    }
}

// ---------------------------------------------------------------------------
// Split fp32 -> fp16 hi/lo pair.
// ---------------------------------------------------------------------------
__global__ __launch_bounds__(256)
void k_split(const float* __restrict__ x, __half* __restrict__ h,
             __half* __restrict__ l, int n)
{
    for (int i = blockIdx.x * 256 + threadIdx.x; i < n; i += gridDim.x * 256) {
        float v = x[i];
        __half hh = __float2half_rn(v);
        h[i] = hh;
        l[i] = __float2half_rn(v - __half2float(hh));
    }
}

// ---------------------------------------------------------------------------
// 2-pass row softmax: single exp per element. Writes UNNORMALIZED p=exp(s-m)
// as fp16 for j in [i, S), zeros for [i_tile, i), and inv_l = 1/sum per row.
// Normalization is applied in the PV epilogue via rowscale.
// ---------------------------------------------------------------------------
__global__ __launch_bounds__(256)
void k_softmax(const float* __restrict__ Sc, __half* __restrict__ Ph,
               float* __restrict__ Linv)
{
    int i = blockIdx.x;
    int b = blockIdx.y;
    size_t off = ((size_t)b * Sq + i) * Sq;
    const float* row = Sc + off;
    __half* ph = Ph + off;
    int t = threadIdx.x;
    __shared__ float red[256];

    // pass 1: max over [i, S)
    float m = -3.402823466e38f;
    for (int j = i + t; j < Sq; j += 256) m = fmaxf(m, row[j]);
    red[t] = m; __syncthreads();
    for (int s = 128; s > 0; s >>= 1) {
        if (t < s) red[t] = fmaxf(red[t], red[t + s]);
        __syncthreads();
    }
    m = red[0];
    __syncthreads();

    // pass 2: exp once, write unnormalized p, accumulate sum
    float l = 0.f;
    for (int j = i + t; j < Sq; j += 256) {
        float e = __expf(row[j] - m);
        l += e;
        ph[j] = __float2half_rn(e);
    }
    // zero the masked prefix within this row's PV k-tile
    int i0 = i & ~(BM - 1);
    for (int j = i0 + t; j < i; j += 256) ph[j] = __float2half_rn(0.f);

    red[t] = l; __syncthreads();
    for (int s = 128; s > 0; s >>= 1) {
        if (t < s) red[t] += red[t + s];
        __syncthreads();
    }
    if (t == 0) Linv[(size_t)b * Sq + i] = 1.0f / red[0];
}

// ---------------------------------------------------------------------------
// Transpose v [S,H] -> vt [H,S] per batch, splitting to fp16 hi/lo.
// ---------------------------------------------------------------------------
__global__ __launch_bounds__(256)
void k_transpose_split(const float* __restrict__ V, __half* __restrict__ Th,
                       __half* __restrict__ Tl)
{
    __shared__ float t[32][33];
    int bz = blockIdx.z;
    const float* Vb = V + (size_t)bz * Sq * Hh;
    __half* Hb = Th + (size_t)bz * Sq * Hh;
    __half* Lb = Tl + (size_t)bz * Sq * Hh;
    int c0 = blockIdx.x * 32, r0 = blockIdx.y * 32;
    int tx = threadIdx.x & 31, ty = threadIdx.x >> 5;
    #pragma unroll
    for (int i = ty; i < 32; i += 8)
        t[i][tx] = Vb[(size_t)(r0 + i) * Hh + c0 + tx];
    __syncthreads();
    #pragma unroll
    for (int i = ty; i < 32; i += 8) {
        float v = t[tx][i];
        __half h = __float2half_rn(v);
        size_t o = (size_t)(c0 + i) * Sq + r0 + tx;
        Hb[o] = h;
        Lb[o] = __float2half_rn(v - __half2float(h));
    }
}

// ---------------------------------------------------------------------------
extern "C" void kernel_launch(void* const* d_in, const int* in_sizes, int n_in,
                              void* d_out, int out_size)
{
    (void)in_sizes; (void)n_in; (void)out_size;
    const float* x  = (const float*)d_in[0];
    const float* Wq = (const float*)d_in[1];
    const float* bq = (const float*)d_in[2];
    const float* Wk = (const float*)d_in[3];
    const float* bk = (const float*)d_in[4];
    const float* Wv = (const float*)d_in[5];
    const float* bv = (const float*)d_in[6];
    const float* Wm = (const float*)d_in[7];
    const float* bm = (const float*)d_in[8];
    float* out = (float*)d_out;

    __half *xh, *xl, *Wqh, *Wql, *Wkh, *Wkl, *Wvh, *Wvl, *Wmh, *Wml;
    __half *qh, *ql, *kh, *kl, *vth, *vtl, *ph, *ath, *atl;
    float *v, *sc, *linv;
    cudaGetSymbolAddress((void**)&xh,  g_xh);  cudaGetSymbolAddress((void**)&xl,  g_xl);
    cudaGetSymbolAddress((void**)&Wqh, g_Wqh); cudaGetSymbolAddress((void**)&Wql, g_Wql);
    cudaGetSymbolAddress((void**)&Wkh, g_Wkh); cudaGetSymbolAddress((void**)&Wkl, g_Wkl);
    cudaGetSymbolAddress((void**)&Wvh, g_Wvh); cudaGetSymbolAddress((void**)&Wvl, g_Wvl);
    cudaGetSymbolAddress((void**)&Wmh, g_Wmh); cudaGetSymbolAddress((void**)&Wml, g_Wml);
    cudaGetSymbolAddress((void**)&qh,  g_qh);  cudaGetSymbolAddress((void**)&ql,  g_ql);
    cudaGetSymbolAddress((void**)&kh,  g_kh);  cudaGetSymbolAddress((void**)&kl,  g_kl);
    cudaGetSymbolAddress((void**)&v,   g_v);
    cudaGetSymbolAddress((void**)&vth, g_vth); cudaGetSymbolAddress((void**)&vtl, g_vtl);
    cudaGetSymbolAddress((void**)&sc,  g_sc);
    cudaGetSymbolAddress((void**)&ph,  g_ph);
    cudaGetSymbolAddress((void**)&linv,g_linv);
    cudaGetSymbolAddress((void**)&ath, g_ath); cudaGetSymbolAddress((void**)&atl, g_atl);

    cudaFuncSetAttribute(k_hgemm, cudaFuncAttributeMaxDynamicSharedMemorySize, SMEM_SZ);

    dim3 blk(512);

    // Split inputs once.
    k_split<<<2048, 256>>>(x,  xh,  xl,  Bsz * Sq * Dd);
    k_split<<<256,  256>>>(Wq, Wqh, Wql, Dd * Hh);
    k_split<<<256,  256>>>(Wk, Wkh, Wkl, Dd * Hh);
    k_split<<<256,  256>>>(Wv, Wvh, Wvl, Dd * Hh);
    k_split<<<256,  256>>>(Wm, Wmh, Wml, Hh * Hh);

    dim3 gproj(Hh / BN, (Bsz * Sq) / BM, 1);      // 4 x 64

    // Projections (softmax 1/8 folded into q, incl. its bias).
    k_hgemm<<<gproj, blk, SMEM_SZ>>>(xh, xl, Wqh, Wql, bq, (float*)0, (float*)0, qh, ql,
                                     Bsz * Sq, Hh, Dd, 0.125f, 0.125f, 0, 0, 0, 0, 0);
    k_hgemm<<<gproj, blk, SMEM_SZ>>>(xh, xl, Wkh, Wkl, bk, (float*)0, (float*)0, kh, kl,
                                     Bsz * Sq, Hh, Dd, 1.0f, 1.0f, 0, 0, 0, 0, 0);
    k_hgemm<<<gproj, blk, SMEM_SZ>>>(xh, xl, Wvh, Wvl, bv, (float*)0, v, (__half*)0, (__half*)0,
                                     Bsz * Sq, Hh, Dd, 1.0f, 1.0f, 0, 0, 0, 0, 0);

    // Scores (fp32), upper-triangular blocks only (nb >= mb).
    k_hgemm<<<dim3(Sq / BN, Sq / BM, Bsz), blk, SMEM_SZ>>>(
        qh, ql, kh, kl, (const float*)0, (float*)0, sc, (__half*)0, (__half*)0,
        Sq, Sq, Hh, 1.0f, 0.0f,
        (long long)Sq * Hh, (long long)Sq * Hh, (long long)Sq * Sq, 1, 0);

    // 2-pass softmax -> unnormalized fp16 probs + inv rowsum.
    k_softmax<<<dim3(Sq, Bsz), 256>>>(sc, ph, linv);

    // vt = v^T (split), then attn = (P @ v) * inv_l, 2-term.
    // Default raster order runs mb=0 (heaviest: k range [0, S)) first.
    k_transpose_split<<<dim3(Hh / 32, Sq / 32, Bsz), 256>>>(v, vth, vtl);
    k_hgemm<<<dim3(Hh / BN, Sq / BM, Bsz), blk, SMEM_SZ>>>(
        ph, (__half*)0, vth, vtl, (const float*)0, linv, (float*)0, ath, atl,
        Sq, Hh, Sq, 1.0f, 0.0f,
        (long long)Sq * Sq, (long long)Sq * Hh, (long long)Sq * Hh, 0, 1);

    // out = 8 * attn @ Wm^T + bm  (NUM_HEADS folded into scale).
    k_hgemm<<<gproj, blk, SMEM_SZ>>>(ath, atl, Wmh, Wml, bm, (float*)0, out, (__half*)0, (__half*)0,
                                     Bsz * Sq, Hh, Dd, 8.0f, 1.0f, 0, 0, 0, 0, 0);
}